// round 12
// baseline (speedup 1.0000x reference)
#include <cuda_runtime.h>

#define H      20
#define NEX    13
#define EMBD   3
#define FIN    3
#define FOUT   5
#define HIN    8
#define HID    10
#define BLK    128
#define RPB    256        // rows per block (2 per thread)
#define FROW   (H*FIN)    // 60 floats of f per row
#define WSTR   48         // per-head packed weight stride (floats)
#define ESTR   12         // E' row stride (floats) -> 48B
#define FSTR   61         // s_f row stride (odd -> conflict-free LDS.32)

typedef unsigned long long u64;

// g_E[(h*NEX+idx)*12 + j] = emb[idx]@W1[h][0:3,j] + b1[h][j] + bf@W1[h][3:8,j]  (j<10, pad 0)
// c_W[h*48 + c*12 + j] = (Wf @ W1[h][3:8])[c][j]  (c=0..2, j<10, pad 0)
// c_W[h*48 + 36 + j]   = W2[h][j] (j=0..9);  [46]=b2[h];  [47]=Wo[h]
__device__   __align__(16) float g_E[H * NEX * ESTR];   // 3120 floats
__device__   __align__(16) float g_W[H * WSTR];         // 960 floats
__constant__ __align__(16) float c_W[H * WSTR];

__global__ void prep_kernel(const float* __restrict__ emb,
                            const float* __restrict__ Wf,
                            const float* __restrict__ bf,
                            const float* __restrict__ W1,
                            const float* __restrict__ b1,
                            const float* __restrict__ W2,
                            const float* __restrict__ b2,
                            const float* __restrict__ Wo)
{
    const int g = blockIdx.x * blockDim.x + threadIdx.x;
    const int NE = H * NEX * ESTR;          // 3120
    if (g < NE) {
        const int h   = g / (NEX * ESTR);
        const int r   = g % (NEX * ESTR);
        const int idx = r / ESTR;
        const int j   = r % ESTR;
        float v = 0.0f;
        if (j < HID) {
            v = b1[h * HID + j];
#pragma unroll
            for (int k = 0; k < FOUT; k++)
                v = fmaf(bf[k], W1[(h * HIN + 3 + k) * HID + j], v);
#pragma unroll
            for (int d = 0; d < EMBD; d++)
                v = fmaf(emb[idx * EMBD + d], W1[(h * HIN + d) * HID + j], v);
        }
        g_E[g] = v;
    } else if (g < NE + H * WSTR) {
        const int w = g - NE;
        const int h = w / WSTR;
        const int j = w % WSTR;
        float v = 0.0f;
        if (j < 36) {
            const int c  = j / 12;
            const int jj = j % 12;
            if (jj < HID) {
#pragma unroll
                for (int k = 0; k < FOUT; k++)
                    v = fmaf(Wf[c * FOUT + k], W1[(h * HIN + 3 + k) * HID + jj], v);
            }
        } else if (j < 46) {
            v = W2[h * HID + (j - 36)];
        } else if (j == 46) {
            v = b2[h];
        } else {
            v = Wo[h];
        }
        g_W[w] = v;
    }
}

__device__ __forceinline__ double ffma2(double a, double b, double c) {
    double d; asm("fma.rn.f32x2 %0, %1, %2, %3;" : "=d"(d) : "d"(a), "d"(b), "d"(c)); return d;
}
union D2 { double d; float2 f; u64 u; };
#define ABS2(x) ((x) & 0x7FFFFFFF7FFFFFFFULL)

// dynamic shared layout (78016 bytes total)
#define OFF_E  0
#define OFF_F  (H * NEX * ESTR * 4)                 // 12480
#define OFF_I  (OFF_F + RPB * FSTR * 4)             // 74944
#define SMEMSZ (OFF_I + RPB * 3 * 4)                // 78016

__global__ __launch_bounds__(BLK, 2)
void airfit_main(const int*   __restrict__ e,
                 const float* __restrict__ f,
                 const float* __restrict__ bo,
                 float*       __restrict__ out,
                 int n)
{
    extern __shared__ __align__(16) char smem_raw[];
    float*        s_E = reinterpret_cast<float*>(smem_raw + OFF_E);
    float*        s_f = reinterpret_cast<float*>(smem_raw + OFF_F);
    unsigned int* s_e = reinterpret_cast<unsigned int*>(smem_raw + OFF_I);

    const int tid = threadIdx.x;
    const long long b0 = (long long)blockIdx.x * RPB;
    const long long r0 = b0 + tid;
    const long long r1 = b0 + tid + BLK;
    const bool act0 = (r0 < n);
    const bool act1 = (r1 < n);

    int rows = n - (int)b0;
    if (rows > RPB) rows = RPB;
    if (rows < 0)   rows = 0;

    // ---- stage E' (uniform float4 copies, 780 f4) ----
    {
        const float4* src = reinterpret_cast<const float4*>(g_E);
        float4*       dst = reinterpret_cast<float4*>(s_E);
        for (int i = tid; i < H * NEX * ESTR / 4; i += BLK) dst[i] = src[i];
    }

    // ---- stage e: coalesced int4 loads, 4-bit packed indices (idx < 13) ----
    {
        const int nv = rows * 3;                     // 3 words per row
        for (int v = tid; v < nv; v += BLK) {
            const int r = v / 3;
            const int w = v % 3;
            const int* ebase = e + (b0 + r) * H + w * 8;
            const int4 a = *reinterpret_cast<const int4*>(ebase);
            unsigned word = (unsigned)a.x | ((unsigned)a.y << 4)
                          | ((unsigned)a.z << 8) | ((unsigned)a.w << 12);
            if (w < 2) {
                const int4 c = *reinterpret_cast<const int4*>(ebase + 4);
                word |= ((unsigned)c.x << 16) | ((unsigned)c.y << 20)
                      | ((unsigned)c.z << 24) | ((unsigned)c.w << 28);
            }
            s_e[r * 3 + w] = word;
        }
    }

    // ---- stage f coalesced float4 -> stride-61 rows ----
    {
        const float4* fg = reinterpret_cast<const float4*>(f + b0 * FROW);
        const int nf4 = rows * (FROW / 4);           // rows*15
        for (int v = tid; v < nf4; v += BLK) {
            float4 val = fg[v];
            const int row = v / 15;
            const int col = 4 * (v % 15);
            float* dst = &s_f[row * FSTR + col];
            dst[0] = val.x; dst[1] = val.y; dst[2] = val.z; dst[3] = val.w;
        }
    }
    __syncthreads();

    // prefetch both rows' packed indices
    unsigned ew0[3], ew1[3];
#pragma unroll
    for (int c = 0; c < 3; c++) {
        ew0[c] = s_e[tid * 3 + c];
        ew1[c] = s_e[(tid + BLK) * 3 + c];
    }
    const float* myf0 = &s_f[tid * FSTR];
    const float* myf1 = &s_f[(tid + BLK) * FSTR];

    const float bov = __ldg(bo);
    float acc0 = bov, acc1 = bov;

#pragma unroll
    for (int h = 0; h < H; h++) {
        const int i0 = (int)((ew0[h >> 3] >> ((h & 7) * 4)) & 0xF);
        const int i1 = (int)((ew1[h >> 3] >> ((h & 7) * 4)) & 0xF);

        // accumulators from bias-folded embedding table (both rows)
        const float* E0 = &s_E[(h * NEX + i0) * ESTR];
        const float* E1 = &s_E[(h * NEX + i1) * ESTR];
        const double2 ea0 = *reinterpret_cast<const double2*>(E0);
        const double2 eb0 = *reinterpret_cast<const double2*>(E0 + 4);
        double s4 = *reinterpret_cast<const double*>(E0 + 8);
        const double2 ea1 = *reinterpret_cast<const double2*>(E1);
        const double2 eb1 = *reinterpret_cast<const double2*>(E1 + 4);
        double u4 = *reinterpret_cast<const double*>(E1 + 8);
        double s0 = ea0.x, s1 = ea0.y, s2 = eb0.x, s3 = eb0.y;
        double u0 = ea1.x, u1 = ea1.y, u2 = eb1.x, u3 = eb1.y;

#pragma unroll
        for (int c = 0; c < 3; c++) {
            // one set of weight loads serves both rows
            const double2 wa = *reinterpret_cast<const double2*>(&c_W[h * WSTR + c * 12]);
            const double2 wb = *reinterpret_cast<const double2*>(&c_W[h * WSTR + c * 12 + 4]);
            const double  wc = *reinterpret_cast<const double*>(&c_W[h * WSTR + c * 12 + 8]);
            const float fc0 = myf0[h * 3 + c];
            const float fc1 = myf1[h * 3 + c];
            D2 p0; p0.f = make_float2(fc0, fc0);
            D2 p1; p1.f = make_float2(fc1, fc1);
            s0 = ffma2(p0.d, wa.x, s0);  u0 = ffma2(p1.d, wa.x, u0);
            s1 = ffma2(p0.d, wa.y, s1);  u1 = ffma2(p1.d, wa.y, u1);
            s2 = ffma2(p0.d, wb.x, s2);  u2 = ffma2(p1.d, wb.x, u2);
            s3 = ffma2(p0.d, wb.y, s3);  u3 = ffma2(p1.d, wb.y, u3);
            s4 = ffma2(p0.d, wc,   s4);  u4 = ffma2(p1.d, wc,   u4);
        }

        // W2 / b2 / Wo (3 loads, shared)
        const double2 V0 = *reinterpret_cast<const double2*>(&c_W[h * WSTR + 36]); // w2 0..3
        const double2 V1 = *reinterpret_cast<const double2*>(&c_W[h * WSTR + 40]); // w2 4..7
        const double2 V2 = *reinterpret_cast<const double2*>(&c_W[h * WSTR + 44]); // w2 8,9|b2,Wo
        D2 tail; tail.d = V2.y;                       // .f.x = b2, .f.y = Wo

        // z = 0.505*sum(w2*t) + 0.495*sum(w2*|t|) + b2   (leaky fold after dot)
        D2 za0; za0.u = 0; D2 zb0; zb0.u = 0;
        D2 za1; za1.u = 0; D2 zb1; zb1.u = 0;
        D2 x0, x1, x2, x3, x4;

        za0.d = ffma2(s0, V0.x, za0.d);  za1.d = ffma2(u0, V0.x, za1.d);
        za0.d = ffma2(s1, V0.y, za0.d);  za1.d = ffma2(u1, V0.y, za1.d);
        za0.d = ffma2(s2, V1.x, za0.d);  za1.d = ffma2(u2, V1.x, za1.d);
        za0.d = ffma2(s3, V1.y, za0.d);  za1.d = ffma2(u3, V1.y, za1.d);
        za0.d = ffma2(s4, V2.x, za0.d);  za1.d = ffma2(u4, V2.x, za1.d);

        x0.d = s0; x1.d = s1; x2.d = s2; x3.d = s3; x4.d = s4;
        x0.u = ABS2(x0.u); x1.u = ABS2(x1.u); x2.u = ABS2(x2.u);
        x3.u = ABS2(x3.u); x4.u = ABS2(x4.u);
        zb0.d = ffma2(x0.d, V0.x, zb0.d);
        zb0.d = ffma2(x1.d, V0.y, zb0.d);
        zb0.d = ffma2(x2.d, V1.x, zb0.d);
        zb0.d = ffma2(x3.d, V1.y, zb0.d);
        zb0.d = ffma2(x4.d, V2.x, zb0.d);

        x0.d = u0; x1.d = u1; x2.d = u2; x3.d = u3; x4.d = u4;
        x0.u = ABS2(x0.u); x1.u = ABS2(x1.u); x2.u = ABS2(x2.u);
        x3.u = ABS2(x3.u); x4.u = ABS2(x4.u);
        zb1.d = ffma2(x0.d, V0.x, zb1.d);
        zb1.d = ffma2(x1.d, V0.y, zb1.d);
        zb1.d = ffma2(x2.d, V1.x, zb1.d);
        zb1.d = ffma2(x3.d, V1.y, zb1.d);
        zb1.d = ffma2(x4.d, V2.x, zb1.d);

        const float z0 = fmaf(0.505f, za0.f.x + za0.f.y,
                         fmaf(0.495f, zb0.f.x + zb0.f.y, tail.f.x));
        const float z1 = fmaf(0.505f, za1.f.x + za1.f.y,
                         fmaf(0.495f, zb1.f.x + zb1.f.y, tail.f.x));

        // softplus = max(z,0) + log1p(exp(-|z|))
        const float sp0 = fmaxf(z0, 0.0f) + __logf(1.0f + __expf(-fabsf(z0)));
        const float sp1 = fmaxf(z1, 0.0f) + __logf(1.0f + __expf(-fabsf(z1)));
        acc0 = fmaf(sp0, tail.f.y, acc0);
        acc1 = fmaf(sp1, tail.f.y, acc1);
    }

    if (act0) out[r0] = acc0;
    if (act1) out[r1] = acc1;
}

extern "C" void kernel_launch(void* const* d_in, const int* in_sizes, int n_in,
                              void* d_out, int out_size)
{
    const int*   e   = (const int*)  d_in[0];
    const float* f   = (const float*)d_in[1];
    const float* emb = (const float*)d_in[2];
    const float* Wf  = (const float*)d_in[3];
    const float* bf  = (const float*)d_in[4];
    const float* W1  = (const float*)d_in[5];
    const float* b1  = (const float*)d_in[6];
    const float* W2  = (const float*)d_in[7];
    const float* b2  = (const float*)d_in[8];
    const float* Wo  = (const float*)d_in[9];
    const float* bo  = (const float*)d_in[10];
    float* out = (float*)d_out;

    const int n = in_sizes[0] / H;

    const int prep_elems = H * NEX * ESTR + H * WSTR;   // 4080
    prep_kernel<<<(prep_elems + 255) / 256, 256>>>(emb, Wf, bf, W1, b1, W2, b2, Wo);

    void* gW_dev = nullptr;
    cudaGetSymbolAddress(&gW_dev, g_W);
    cudaMemcpyToSymbolAsync(c_W, gW_dev, sizeof(float) * H * WSTR, 0,
                            cudaMemcpyDeviceToDevice, 0);

    static bool attr_set = false;
    if (!attr_set) {
        cudaFuncSetAttribute(airfit_main,
                             cudaFuncAttributeMaxDynamicSharedMemorySize, SMEMSZ);
        attr_set = true;
    }

    const int grid = (n + RPB - 1) / RPB;
    airfit_main<<<grid, BLK, SMEMSZ>>>(e, f, bo, out, n);
}

// round 13
// speedup vs baseline: 1.1335x; 1.1335x over previous
#include <cuda_runtime.h>

#define H      20
#define NEX    13
#define EMBD   3
#define FIN    3
#define FOUT   5
#define HIN    8
#define HID    10
#define BLK    256        // threads: 2 warps-groups x 128 rows
#define ROWS   128        // rows per block
#define FROW   (H*FIN)    // 60 floats of f per row
#define WSTR   48         // per-head packed weight stride (floats)
#define ESTR   10         // E' row stride (floats) -> 40B, 8B-aligned rows
#define FSTR   61         // s_f row stride (odd -> conflict-free LDS.32)

typedef unsigned long long u64;

// g_E[(h*NEX+idx)*10 + j] = emb[idx]@W1[h][0:3,j] + b1[h][j] + bf@W1[h][3:8,j]
// c_W[h*48 + c*12 + j] = (Wf @ W1[h][3:8])[c][j]  (c=0..2, j<10, pad 0)
// c_W[h*48 + 36 + j]   = W2[h][j] (j=0..9);  [46]=b2[h];  [47]=Wo[h]
__device__   __align__(16) float g_E[H * NEX * ESTR];   // 2600 floats
__device__   __align__(16) float g_W[H * WSTR];         // 960 floats
__constant__ __align__(16) float c_W[H * WSTR];

__global__ void prep_kernel(const float* __restrict__ emb,
                            const float* __restrict__ Wf,
                            const float* __restrict__ bf,
                            const float* __restrict__ W1,
                            const float* __restrict__ b1,
                            const float* __restrict__ W2,
                            const float* __restrict__ b2,
                            const float* __restrict__ Wo)
{
    const int g = blockIdx.x * blockDim.x + threadIdx.x;
    const int NE = H * NEX * ESTR;          // 2600
    if (g < NE) {
        const int h   = g / (NEX * ESTR);
        const int r   = g % (NEX * ESTR);
        const int idx = r / ESTR;
        const int j   = r % ESTR;
        float v = b1[h * HID + j];
#pragma unroll
        for (int k = 0; k < FOUT; k++)
            v = fmaf(bf[k], W1[(h * HIN + 3 + k) * HID + j], v);
#pragma unroll
        for (int d = 0; d < EMBD; d++)
            v = fmaf(emb[idx * EMBD + d], W1[(h * HIN + d) * HID + j], v);
        g_E[g] = v;
    } else if (g < NE + H * WSTR) {
        const int w = g - NE;
        const int h = w / WSTR;
        const int j = w % WSTR;
        float v = 0.0f;
        if (j < 36) {
            const int c  = j / 12;
            const int jj = j % 12;
            if (jj < HID) {
#pragma unroll
                for (int k = 0; k < FOUT; k++)
                    v = fmaf(Wf[c * FOUT + k], W1[(h * HIN + 3 + k) * HID + jj], v);
            }
        } else if (j < 46) {
            v = W2[h * HID + (j - 36)];
        } else if (j == 46) {
            v = b2[h];
        } else {
            v = Wo[h];
        }
        g_W[w] = v;
    }
}

__device__ __forceinline__ double ffma2(double a, double b, double c) {
    double d; asm("fma.rn.f32x2 %0, %1, %2, %3;" : "=d"(d) : "d"(a), "d"(b), "d"(c)); return d;
}
union D2 { double d; float2 f; u64 u; };
#define ABS2(x) ((x) & 0x7FFFFFFF7FFFFFFFULL)

// dynamic shared layout: 43680 bytes total -> 4 CTAs/SM (32 warps)
#define OFF_E  0
#define OFF_F  (H * NEX * ESTR * 4)                 // 10400
#define OFF_I  (OFF_F + ROWS * FSTR * 4)            // 41632
#define OFF_P  (OFF_I + ROWS * 3 * 4)               // 43168
#define SMEMSZ (OFF_P + ROWS * 4)                   // 43680

__global__ __launch_bounds__(BLK, 4)
void airfit_main(const int*   __restrict__ e,
                 const float* __restrict__ f,
                 const float* __restrict__ bo,
                 float*       __restrict__ out,
                 int n)
{
    extern __shared__ __align__(16) char smem_raw[];
    float*        s_E = reinterpret_cast<float*>(smem_raw + OFF_E);
    float*        s_f = reinterpret_cast<float*>(smem_raw + OFF_F);
    unsigned int* s_e = reinterpret_cast<unsigned int*>(smem_raw + OFF_I);
    float*        s_p = reinterpret_cast<float*>(smem_raw + OFF_P);

    const int tid  = threadIdx.x;
    const int row  = tid & (ROWS - 1);
    const int half = tid >> 7;                      // uniform per warp
    const long long b0 = (long long)blockIdx.x * ROWS;
    const bool active = (b0 + row < n);

    int rows = n - (int)b0;
    if (rows > ROWS) rows = ROWS;
    if (rows < 0)    rows = 0;

    // ---- stage E' (uniform float4 copies, 650 f4) ----
    {
        const float4* src = reinterpret_cast<const float4*>(g_E);
        float4*       dst = reinterpret_cast<float4*>(s_E);
        for (int i = tid; i < H * NEX * ESTR / 4; i += BLK) dst[i] = src[i];
    }

    // ---- stage e: coalesced int4 loads, 4-bit packed indices (idx < 13) ----
    {
        const int nv = rows * 3;                    // 3 words per row
        for (int v = tid; v < nv; v += BLK) {
            const int r = v / 3;
            const int w = v % 3;
            const int* ebase = e + (b0 + r) * H + w * 8;
            const int4 a = *reinterpret_cast<const int4*>(ebase);
            unsigned word = (unsigned)a.x | ((unsigned)a.y << 4)
                          | ((unsigned)a.z << 8) | ((unsigned)a.w << 12);
            if (w < 2) {
                const int4 c = *reinterpret_cast<const int4*>(ebase + 4);
                word |= ((unsigned)c.x << 16) | ((unsigned)c.y << 20)
                      | ((unsigned)c.z << 24) | ((unsigned)c.w << 28);
            }
            s_e[r * 3 + w] = word;
        }
    }

    // ---- stage f coalesced float4 -> stride-61 rows ----
    {
        const float4* fg = reinterpret_cast<const float4*>(f + b0 * FROW);
        const int nf4 = rows * (FROW / 4);          // rows*15
        for (int v = tid; v < nf4; v += BLK) {
            float4 val = fg[v];
            const int r   = v / 15;
            const int col = 4 * (v % 15);
            float* dst = &s_f[r * FSTR + col];
            dst[0] = val.x; dst[1] = val.y; dst[2] = val.z; dst[3] = val.w;
        }
    }
    __syncthreads();

    float acc = 0.0f;

    {
        // my 10 nibble indices, pre-shifted into one u64 (constant shifts below)
        const unsigned ew0 = s_e[row * 3 + 0];
        const unsigned ew1 = s_e[row * 3 + 1];
        const unsigned ew2 = s_e[row * 3 + 2];
        const u64 mynib = half ? (((u64)(ew1 >> 8)) | ((u64)ew2 << 24))
                               : (((u64)ew0) | ((u64)ew1 << 32));

        const float* myf   = &s_f[row * FSTR + half * 30];
        const float* Wbase = c_W + half * 10 * WSTR;        // warp-uniform
        const float* Ebase = s_E + half * 10 * NEX * ESTR;

#pragma unroll
        for (int hh = 0; hh < 10; hh++) {
            const int idx = (int)((mynib >> (hh * 4)) & 0xF);

            // accumulators from bias-folded embedding table (5x LDS.64)
            const float* Ep = Ebase + (hh * NEX + idx) * ESTR;
            double t0 = *reinterpret_cast<const double*>(Ep + 0);
            double t1 = *reinterpret_cast<const double*>(Ep + 2);
            double t2 = *reinterpret_cast<const double*>(Ep + 4);
            double t3 = *reinterpret_cast<const double*>(Ep + 6);
            double t4 = *reinterpret_cast<const double*>(Ep + 8);

            const float* Wh = Wbase + hh * WSTR;
#pragma unroll
            for (int c = 0; c < 3; c++) {
                const double2 wa = *reinterpret_cast<const double2*>(Wh + c * 12);
                const double2 wb = *reinterpret_cast<const double2*>(Wh + c * 12 + 4);
                const double  wc = *reinterpret_cast<const double*>(Wh + c * 12 + 8);
                const float fc = myf[hh * 3 + c];
                D2 p; p.f = make_float2(fc, fc);
                t0 = ffma2(p.d, wa.x, t0);
                t1 = ffma2(p.d, wa.y, t1);
                t2 = ffma2(p.d, wb.x, t2);
                t3 = ffma2(p.d, wb.y, t3);
                t4 = ffma2(p.d, wc,   t4);
            }

            // W2 / b2 / Wo (3 loads); post-dot leaky fold:
            // z = 0.505*sum(w2*t) + 0.495*sum(w2*|t|) + b2
            const double2 V0 = *reinterpret_cast<const double2*>(Wh + 36);
            const double2 V1 = *reinterpret_cast<const double2*>(Wh + 40);
            const double2 V2 = *reinterpret_cast<const double2*>(Wh + 44); // w2 8,9 | b2,Wo
            D2 tail; tail.d = V2.y;                  // .f.x = b2, .f.y = Wo

            D2 za; za.u = 0;
            D2 zb; zb.u = 0;
            za.d = ffma2(t0, V0.x, za.d);
            za.d = ffma2(t1, V0.y, za.d);
            za.d = ffma2(t2, V1.x, za.d);
            za.d = ffma2(t3, V1.y, za.d);
            za.d = ffma2(t4, V2.x, za.d);

            D2 x0, x1, x2, x3, x4;
            x0.d = t0; x1.d = t1; x2.d = t2; x3.d = t3; x4.d = t4;
            x0.u = ABS2(x0.u); x1.u = ABS2(x1.u); x2.u = ABS2(x2.u);
            x3.u = ABS2(x3.u); x4.u = ABS2(x4.u);
            zb.d = ffma2(x0.d, V0.x, zb.d);
            zb.d = ffma2(x1.d, V0.y, zb.d);
            zb.d = ffma2(x2.d, V1.x, zb.d);
            zb.d = ffma2(x3.d, V1.y, zb.d);
            zb.d = ffma2(x4.d, V2.x, zb.d);

            const float z = fmaf(0.505f, za.f.x + za.f.y,
                            fmaf(0.495f, zb.f.x + zb.f.y, tail.f.x));

            // softplus = max(z,0) + log1p(exp(-|z|))
            const float sp = fmaxf(z, 0.0f) + __logf(1.0f + __expf(-fabsf(z)));
            acc = fmaf(sp, tail.f.y, acc);
        }
    }

    // combine halves: warps 4-7 publish, warps 0-3 reduce + write
    if (half) s_p[row] = acc;
    __syncthreads();
    if (!half && active)
        out[b0 + row] = acc + s_p[row] + __ldg(bo);
}

extern "C" void kernel_launch(void* const* d_in, const int* in_sizes, int n_in,
                              void* d_out, int out_size)
{
    const int*   e   = (const int*)  d_in[0];
    const float* f   = (const float*)d_in[1];
    const float* emb = (const float*)d_in[2];
    const float* Wf  = (const float*)d_in[3];
    const float* bf  = (const float*)d_in[4];
    const float* W1  = (const float*)d_in[5];
    const float* b1  = (const float*)d_in[6];
    const float* W2  = (const float*)d_in[7];
    const float* b2  = (const float*)d_in[8];
    const float* Wo  = (const float*)d_in[9];
    const float* bo  = (const float*)d_in[10];
    float* out = (float*)d_out;

    const int n = in_sizes[0] / H;

    const int prep_elems = H * NEX * ESTR + H * WSTR;   // 3560
    prep_kernel<<<(prep_elems + 255) / 256, 256>>>(emb, Wf, bf, W1, b1, W2, b2, Wo);

    void* gW_dev = nullptr;
    cudaGetSymbolAddress(&gW_dev, g_W);
    cudaMemcpyToSymbolAsync(c_W, gW_dev, sizeof(float) * H * WSTR, 0,
                            cudaMemcpyDeviceToDevice, 0);

    static bool attr_set = false;
    if (!attr_set) {
        cudaFuncSetAttribute(airfit_main,
                             cudaFuncAttributeMaxDynamicSharedMemorySize, SMEMSZ);
        attr_set = true;
    }

    const int grid = (n + ROWS - 1) / ROWS;
    airfit_main<<<grid, BLK, SMEMSZ>>>(e, f, bo, out, n);
}

// round 14
// speedup vs baseline: 1.1561x; 1.0199x over previous
#include <cuda_runtime.h>

#define H      20
#define NEX    13
#define EMBD   3
#define FIN    3
#define FOUT   5
#define HIN    8
#define HID    10
#define BLK    128
#define FROW   (H*FIN)    // 60 floats of f per row
#define W1STR  36         // per-head W1 pack stride (floats) in smem
#define VSTR   12         // per-head V pack stride (floats) in constant
#define ESTR   10         // E' row stride (floats)
#define FSTR   61         // s_f row stride (odd -> conflict-free LDS.32)

typedef unsigned long long u64;

// g_E[(h*NEX+idx)*10 + j] = emb[idx]@W1[h][0:3,j] + b1[h][j] + bf@W1[h][3:8,j]
// g_W1[h*36 + c*12 + j]   = (Wf @ W1[h][3:8])[c][j]  (c=0..2, j<10, pads 0)
// g_V[h*12 + j] = W2[h][j] (j<10);  [10]=b2[h];  [11]=Wo[h]
__device__   __align__(16) float g_E [H * NEX * ESTR];  // 2600 floats
__device__   __align__(16) float g_W1[H * W1STR];       // 720 floats
__device__   __align__(16) float g_V [H * VSTR];        // 240 floats
__constant__ __align__(16) float c_V [H * VSTR];

__global__ void prep_kernel(const float* __restrict__ emb,
                            const float* __restrict__ Wf,
                            const float* __restrict__ bf,
                            const float* __restrict__ W1,
                            const float* __restrict__ b1,
                            const float* __restrict__ W2,
                            const float* __restrict__ b2,
                            const float* __restrict__ Wo)
{
    const int g = blockIdx.x * blockDim.x + threadIdx.x;
    const int NE = H * NEX * ESTR;          // 2600
    const int NW = H * W1STR;               // 720
    if (g < NE) {
        const int h   = g / (NEX * ESTR);
        const int r   = g % (NEX * ESTR);
        const int idx = r / ESTR;
        const int j   = r % ESTR;
        float v = b1[h * HID + j];
#pragma unroll
        for (int k = 0; k < FOUT; k++)
            v = fmaf(bf[k], W1[(h * HIN + 3 + k) * HID + j], v);
#pragma unroll
        for (int d = 0; d < EMBD; d++)
            v = fmaf(emb[idx * EMBD + d], W1[(h * HIN + d) * HID + j], v);
        g_E[g] = v;
    } else if (g < NE + NW) {
        const int w = g - NE;
        const int h = w / W1STR;
        const int j = w % W1STR;
        const int c  = j / 12;
        const int jj = j % 12;
        float v = 0.0f;
        if (jj < HID) {
#pragma unroll
            for (int k = 0; k < FOUT; k++)
                v = fmaf(Wf[c * FOUT + k], W1[(h * HIN + 3 + k) * HID + jj], v);
        }
        g_W1[w] = v;
    } else if (g < NE + NW + H * VSTR) {
        const int w = g - NE - NW;
        const int h = w / VSTR;
        const int j = w % VSTR;
        float v;
        if      (j < HID)  v = W2[h * HID + j];
        else if (j == 10)  v = b2[h];
        else               v = Wo[h];
        g_V[w] = v;
    }
}

__device__ __forceinline__ double ffma2(double a, double b, double c) {
    double d; asm("fma.rn.f32x2 %0, %1, %2, %3;" : "=d"(d) : "d"(a), "d"(b), "d"(c)); return d;
}
union D2 { double d; float2 f; u64 u; };
#define ABS2(x) ((x) & 0x7FFFFFFF7FFFFFFFULL)

// dynamic shared layout: 46048 bytes -> 5 CTAs/SM (20 warps)
#define OFF_E  0
#define OFF_W  (H * NEX * ESTR * 4)                 // 10400
#define OFF_F  (OFF_W + H * W1STR * 4)              // 13280
#define OFF_I  (OFF_F + BLK * FSTR * 4)             // 44512
#define SMEMSZ (OFF_I + BLK * 3 * 4)                // 46048

__global__ __launch_bounds__(BLK, 5)
void airfit_main(const int*   __restrict__ e,
                 const float* __restrict__ f,
                 const float* __restrict__ bo,
                 float*       __restrict__ out,
                 int n)
{
    extern __shared__ __align__(16) char smem_raw[];
    float*        s_E = reinterpret_cast<float*>(smem_raw + OFF_E);
    float*        s_W = reinterpret_cast<float*>(smem_raw + OFF_W);
    float*        s_f = reinterpret_cast<float*>(smem_raw + OFF_F);
    unsigned int* s_e = reinterpret_cast<unsigned int*>(smem_raw + OFF_I);

    const int tid = threadIdx.x;
    const long long b0 = (long long)blockIdx.x * BLK;
    const long long b  = b0 + tid;
    const bool active = (b < n);

    int rows = n - (int)b0;
    if (rows > BLK) rows = BLK;
    if (rows < 0)   rows = 0;

    // ---- stage E' + W1 (uniform float4 copies: 650 + 180 f4) ----
    {
        const float4* src = reinterpret_cast<const float4*>(g_E);
        float4*       dst = reinterpret_cast<float4*>(s_E);
        for (int i = tid; i < H * NEX * ESTR / 4; i += BLK) dst[i] = src[i];
        const float4* srcW = reinterpret_cast<const float4*>(g_W1);
        float4*       dstW = reinterpret_cast<float4*>(s_W);
        for (int i = tid; i < H * W1STR / 4; i += BLK) dstW[i] = srcW[i];
    }

    // ---- stage e: coalesced int4 loads, 4-bit packed indices (idx < 13) ----
    {
        const int nv = rows * 3;                    // 3 words per row
        for (int v = tid; v < nv; v += BLK) {
            const int r = v / 3;
            const int w = v % 3;
            const int* ebase = e + (b0 + r) * H + w * 8;
            const int4 a = *reinterpret_cast<const int4*>(ebase);
            unsigned word = (unsigned)a.x | ((unsigned)a.y << 4)
                          | ((unsigned)a.z << 8) | ((unsigned)a.w << 12);
            if (w < 2) {
                const int4 c = *reinterpret_cast<const int4*>(ebase + 4);
                word |= ((unsigned)c.x << 16) | ((unsigned)c.y << 20)
                      | ((unsigned)c.z << 24) | ((unsigned)c.w << 28);
            }
            s_e[r * 3 + w] = word;
        }
    }

    // ---- stage f coalesced float4 -> stride-61 rows ----
    {
        const float4* fg = reinterpret_cast<const float4*>(f + b0 * FROW);
        const int nf4 = rows * (FROW / 4);          // rows*15
        for (int v = tid; v < nf4; v += BLK) {
            float4 val = fg[v];
            const int row = v / 15;
            const int col = 4 * (v % 15);
            float* dst = &s_f[row * FSTR + col];
            dst[0] = val.x; dst[1] = val.y; dst[2] = val.z; dst[3] = val.w;
        }
    }
    __syncthreads();

    if (active) {
        // prefetch this row's 20 nibble-packed indices into 3 registers
        const unsigned ew0 = s_e[tid * 3 + 0];
        const unsigned ew1 = s_e[tid * 3 + 1];
        const unsigned ew2 = s_e[tid * 3 + 2];

        const float* myf = &s_f[tid * FSTR];
        float accA = __ldg(bo);
        float accB = 0.0f;

#pragma unroll
        for (int h = 0; h < H; h++) {
            const unsigned ew = (h < 8) ? ew0 : (h < 16) ? ew1 : ew2;
            const int idx = (int)((ew >> ((h & 7) * 4)) & 0xF);

            // accumulators from bias-folded embedding table (5x LDS.64 gather)
            const float* Ep = &s_E[(h * NEX + idx) * ESTR];
            double t0 = *reinterpret_cast<const double*>(Ep + 0);
            double t1 = *reinterpret_cast<const double*>(Ep + 2);
            double t2 = *reinterpret_cast<const double*>(Ep + 4);
            double t3 = *reinterpret_cast<const double*>(Ep + 6);
            double t4 = *reinterpret_cast<const double*>(Ep + 8);

            // W1 from shared memory: warp-uniform address -> broadcast
            const float* Wh = &s_W[h * W1STR];
#pragma unroll
            for (int c = 0; c < 3; c++) {
                const double2 wa = *reinterpret_cast<const double2*>(Wh + c * 12);
                const double2 wb = *reinterpret_cast<const double2*>(Wh + c * 12 + 4);
                const double  wc = *reinterpret_cast<const double*>(Wh + c * 12 + 8);
                const float fc = myf[h * 3 + c];
                D2 p; p.f = make_float2(fc, fc);
                t0 = ffma2(p.d, wa.x, t0);
                t1 = ffma2(p.d, wa.y, t1);
                t2 = ffma2(p.d, wb.x, t2);
                t3 = ffma2(p.d, wb.y, t3);
                t4 = ffma2(p.d, wc,   t4);
            }

            // W2/b2/Wo from the constant port (3 LDC.128 per head)
            const double2 V0 = *reinterpret_cast<const double2*>(&c_V[h * VSTR + 0]); // w2 0..3
            const double2 V1 = *reinterpret_cast<const double2*>(&c_V[h * VSTR + 4]); // w2 4..7
            const double2 V2 = *reinterpret_cast<const double2*>(&c_V[h * VSTR + 8]); // w2 8,9|b2,Wo
            D2 tail; tail.d = V2.y;                 // .f.x = b2, .f.y = Wo

            // post-dot leaky fold: z = 0.505*sum(w2*t) + 0.495*sum(w2*|t|) + b2
            D2 za; za.u = 0;
            D2 zb; zb.u = 0;
            za.d = ffma2(t0, V0.x, za.d);
            za.d = ffma2(t1, V0.y, za.d);
            za.d = ffma2(t2, V1.x, za.d);
            za.d = ffma2(t3, V1.y, za.d);
            za.d = ffma2(t4, V2.x, za.d);

            D2 x0, x1, x2, x3, x4;
            x0.d = t0; x1.d = t1; x2.d = t2; x3.d = t3; x4.d = t4;
            x0.u = ABS2(x0.u); x1.u = ABS2(x1.u); x2.u = ABS2(x2.u);
            x3.u = ABS2(x3.u); x4.u = ABS2(x4.u);
            zb.d = ffma2(x0.d, V0.x, zb.d);
            zb.d = ffma2(x1.d, V0.y, zb.d);
            zb.d = ffma2(x2.d, V1.x, zb.d);
            zb.d = ffma2(x3.d, V1.y, zb.d);
            zb.d = ffma2(x4.d, V2.x, zb.d);

            const float z = fmaf(0.505f, za.f.x + za.f.y,
                            fmaf(0.495f, zb.f.x + zb.f.y, tail.f.x));

            // softplus = max(z,0) + log1p(exp(-|z|))
            const float sp = fmaxf(z, 0.0f) + __logf(1.0f + __expf(-fabsf(z)));
            if (h & 1) accB = fmaf(sp, tail.f.y, accB);
            else       accA = fmaf(sp, tail.f.y, accA);
        }

        out[b] = accA + accB;
    }
}

extern "C" void kernel_launch(void* const* d_in, const int* in_sizes, int n_in,
                              void* d_out, int out_size)
{
    const int*   e   = (const int*)  d_in[0];
    const float* f   = (const float*)d_in[1];
    const float* emb = (const float*)d_in[2];
    const float* Wf  = (const float*)d_in[3];
    const float* bf  = (const float*)d_in[4];
    const float* W1  = (const float*)d_in[5];
    const float* b1  = (const float*)d_in[6];
    const float* W2  = (const float*)d_in[7];
    const float* b2  = (const float*)d_in[8];
    const float* Wo  = (const float*)d_in[9];
    const float* bo  = (const float*)d_in[10];
    float* out = (float*)d_out;

    const int n = in_sizes[0] / H;

    const int prep_elems = H * NEX * ESTR + H * W1STR + H * VSTR;   // 3560
    prep_kernel<<<(prep_elems + 255) / 256, 256>>>(emb, Wf, bf, W1, b1, W2, b2, Wo);

    void* gV_dev = nullptr;
    cudaGetSymbolAddress(&gV_dev, g_V);
    cudaMemcpyToSymbolAsync(c_V, gV_dev, sizeof(float) * H * VSTR, 0,
                            cudaMemcpyDeviceToDevice, 0);

    static bool attr_set = false;
    if (!attr_set) {
        cudaFuncSetAttribute(airfit_main,
                             cudaFuncAttributeMaxDynamicSharedMemorySize, SMEMSZ);
        attr_set = true;
    }

    const int grid = (n + BLK - 1) / BLK;
    airfit_main<<<grid, BLK, SMEMSZ>>>(e, f, bo, out, n);
}